// round 5
// baseline (speedup 1.0000x reference)
#include <cuda_runtime.h>
#include <cuda_bf16.h>
#include <stdint.h>

// Inputs (metadata order):
//   d_in[0]: inputs_t  int32  [1, n_source]   (n_source = 17400)
//   d_in[1]: indices   int32  [N_SYN, 2]  -> (post, pre) per row
//   d_in[2]: weights   float32 [N_SYN]
//   d_in[3]: n_post    (scalar; we use out_size instead)
// Output: float32 [1, n_post]

#define TILE      1024          // synapses per tile
#define THREADS   256
#define SYN_PER_THREAD (TILE / THREADS)   // 4

// Activity bitmask (device global scratch; rebuilt every call -> deterministic).
__device__ uint32_t g_actbits[65536];

// ---------------------------------------------------------------------------
// Prep: zero output + build activity bitmask in one launch.
// ---------------------------------------------------------------------------
__global__ void __launch_bounds__(256) prep_kernel(
    const int* __restrict__ act, int n_source,
    float* __restrict__ out, int n_out,
    int n_src_padded)
{
    int i = blockIdx.x * blockDim.x + threadIdx.x;
    if (i < n_out) out[i] = 0.0f;
    if (i < n_src_padded) {
        bool active = (i < n_source) && (act[i] > 0);
        unsigned mask = __ballot_sync(0xFFFFFFFFu, active);
        if ((threadIdx.x & 31) == 0) g_actbits[i >> 5] = mask;
    }
}

// ---------------------------------------------------------------------------
// mbarrier / bulk-copy PTX helpers
// ---------------------------------------------------------------------------
__device__ __forceinline__ uint32_t smem_u32(const void* p) {
    uint32_t a;
    asm("{ .reg .u64 t; cvta.to.shared.u64 t, %1; cvt.u32.u64 %0, t; }"
        : "=r"(a) : "l"(p));
    return a;
}

#define MBAR_INIT(addr, cnt) \
    asm volatile("mbarrier.init.shared.b64 [%0], %1;" :: "r"(addr), "r"(cnt) : "memory")

#define MBAR_EXPECT_TX(addr, bytes) \
    asm volatile("mbarrier.arrive.expect_tx.shared.b64 _, [%0], %1;" \
                 :: "r"(addr), "r"(bytes) : "memory")

#define MBAR_WAIT(addr, parity) do {                                          \
    uint32_t _m = (addr), _p = (parity), _d;                                  \
    asm volatile("{\n\t.reg .pred p;\n\t"                                     \
        "mbarrier.try_wait.parity.acquire.cta.shared::cta.b64 p, [%1], %2;\n\t" \
        "selp.b32 %0, 1, 0, p;\n\t}"                                          \
        : "=r"(_d) : "r"(_m), "r"(_p) : "memory");                            \
    if (!_d) {                                                                \
        asm volatile("{\n\t.reg .pred P1;\n\t"                                \
            "WL_%=:\n\t"                                                      \
            "mbarrier.try_wait.parity.acquire.cta.shared::cta.b64 P1, [%0], %1, 0x989680;\n\t" \
            "@P1 bra.uni WD_%=;\n\t"                                          \
            "bra.uni WL_%=;\n\t"                                              \
            "WD_%=:\n\t}"                                                     \
            :: "r"(_m), "r"(_p) : "memory");                                  \
    }                                                                         \
} while (0)

#define BULK_G2S(dst_smem, src_gmem, bytes, mbar) \
    asm volatile("cp.async.bulk.shared::cta.global.mbarrier::complete_tx::bytes " \
                 "[%0], [%1], %2, [%3];"                                      \
                 :: "r"(dst_smem), "l"(src_gmem), "r"(bytes), "r"(mbar) : "memory")

// ---------------------------------------------------------------------------
// SMEM layout (static, 128-aligned regions)
// ---------------------------------------------------------------------------
#define OFF_MBAR   0            // 2 x 8B barriers
#define OFF_BITS   128          // up to 1024 words (4KB) of bitmask
#define OFF_IDX0   4352         // TILE*8 = 8192B
#define OFF_IDX1   12544
#define OFF_W0     20736        // TILE*4 = 4096B
#define OFF_W1     24832
#define SMEM_TOTAL 28928

// ---------------------------------------------------------------------------
// Main scatter: TMA-staged double-buffered pipeline, atomics from smem data.
// ---------------------------------------------------------------------------
__global__ void __launch_bounds__(THREADS) scatter_tma_kernel(
    const char* __restrict__ g_idx,   // indices as bytes (8B per synapse)
    const char* __restrict__ g_w,     // weights as bytes (4B per synapse)
    float*      __restrict__ out,
    int ntiles,
    int n_words)
{
    __shared__ __align__(128) unsigned char smem[SMEM_TOTAL];

    const uint32_t sbase  = smem_u32(smem);
    const uint32_t mbar0  = sbase + OFF_MBAR;
    const uint32_t mbar1  = sbase + OFF_MBAR + 8;
    uint32_t* sbits = (uint32_t*)(smem + OFF_BITS);

    // Load bitmask into smem.
    for (int j = threadIdx.x; j < n_words; j += THREADS)
        sbits[j] = g_actbits[j];

    if (threadIdx.x == 0) {
        MBAR_INIT(mbar0, 1);
        MBAR_INIT(mbar1, 1);
    }
    __syncthreads();

    const int stride = gridDim.x;
    int t = blockIdx.x;                   // first tile for this block
    if (t >= ntiles) return;

    const uint32_t idx_off[2] = { sbase + OFF_IDX0, sbase + OFF_IDX1 };
    const uint32_t w_off[2]   = { sbase + OFF_W0,   sbase + OFF_W1   };
    const uint32_t mb[2]      = { mbar0, mbar1 };
    const uint32_t TILE_IDX_B = TILE * 8;
    const uint32_t TILE_W_B   = TILE * 4;

    // Prefetch first tile into stage 0.
    if (threadIdx.x == 0) {
        MBAR_EXPECT_TX(mb[0], TILE_IDX_B + TILE_W_B);
        BULK_G2S(idx_off[0], g_idx + (size_t)t * TILE_IDX_B, TILE_IDX_B, mb[0]);
        BULK_G2S(w_off[0],   g_w   + (size_t)t * TILE_W_B,   TILE_W_B,   mb[0]);
    }

    int it = 0;
    for (; t < ntiles; t += stride, it++) {
        const int stage = it & 1;
        const int phase = (it >> 1) & 1;

        // Prefetch tile t+stride into the other buffer (consumed & synced last iter).
        const int tn = t + stride;
        if (threadIdx.x == 0 && tn < ntiles) {
            const int os = stage ^ 1;
            MBAR_EXPECT_TX(mb[os], TILE_IDX_B + TILE_W_B);
            BULK_G2S(idx_off[os], g_idx + (size_t)tn * TILE_IDX_B, TILE_IDX_B, mb[os]);
            BULK_G2S(w_off[os],   g_w   + (size_t)tn * TILE_W_B,   TILE_W_B,   mb[os]);
        }

        // Wait for this stage's data.
        MBAR_WAIT(mb[stage], phase);

        const int2*  ib = (const int2*)(smem + (stage ? OFF_IDX1 : OFF_IDX0));
        const float* wb = (const float*)(smem + (stage ? OFF_W1   : OFF_W0));

        #pragma unroll
        for (int k = 0; k < SYN_PER_THREAD; k++) {
            const int e = (k << 8) + threadIdx.x;    // k*256 + tid
            int2  p = ib[e];
            float w = wb[e];
            if ((sbits[(unsigned)p.y >> 5] >> ((unsigned)p.y & 31u)) & 1u)
                atomicAdd(out + p.x, w);
        }

        // Everyone done reading this buffer before it is refilled (2 iters later).
        __syncthreads();
    }
}

// ---------------------------------------------------------------------------
// Tail: synapses beyond ntiles*TILE, plain loads.
// ---------------------------------------------------------------------------
__global__ void scatter_tail_kernel(
    const int2* __restrict__ idx2,
    const float* __restrict__ w,
    float*       __restrict__ out,
    int start, int n_syn)
{
    int i = start + blockIdx.x * blockDim.x + threadIdx.x;
    if (i >= n_syn) return;
    int2 p = idx2[i];
    if ((g_actbits[(unsigned)p.y >> 5] >> ((unsigned)p.y & 31u)) & 1u)
        atomicAdd(out + p.x, w[i]);
}

// ---------------------------------------------------------------------------
extern "C" void kernel_launch(void* const* d_in, const int* in_sizes, int n_in,
                              void* d_out, int out_size) {
    const int*   act     = (const int*)d_in[0];
    const char*  indices = (const char*)d_in[1];
    const char*  weights = (const char*)d_in[2];
    float*       out     = (float*)d_out;

    const int n_source = in_sizes[0];
    const int n_syn    = in_sizes[2];

    const int n_src_padded = (n_source + 31) & ~31;
    int n_words = n_src_padded >> 5;
    if (n_words > 1024) n_words = 1024;   // smem bitmask capacity (32K sources)

    // Prep: zero output + build bitmask.
    {
        int span    = out_size > n_src_padded ? out_size : n_src_padded;
        int threads = 256;
        int blocks  = (span + threads - 1) / threads;
        prep_kernel<<<blocks, threads>>>(act, n_source, out, out_size, n_src_padded);
    }

    const int ntiles = n_syn / TILE;
    if (ntiles > 0) {
        int blocks = ntiles < 888 ? ntiles : 888;   // ~6 CTAs/SM persistent-ish
        scatter_tma_kernel<<<blocks, THREADS>>>(indices, weights, out, ntiles, n_words);
    }

    const int done = ntiles * TILE;
    if (done < n_syn) {
        int rem = n_syn - done;
        int threads = 256;
        int blocks  = (rem + threads - 1) / threads;
        scatter_tail_kernel<<<blocks, threads>>>(
            (const int2*)indices, (const float*)weights, out, done, n_syn);
    }
}